// round 17
// baseline (speedup 1.0000x reference)
#include <cuda_runtime.h>
#include <math.h>

// Problem constants
#define T_STEPS 16384
#define HID     1024
#define INP     256
#define NLAB    32

#define NCTA    128          // persistent CTAs, one per SM, single wave
#define WPC     8            // warps per CTA; NCTA*WPC == HID rows (1 warp : 1 row)
#define TPB     (WPC * 32)   // 256
#define WPT     (HID / TPB)  // tagged words polled per thread = 4

// Tagged hidden state: word = (float_bits(h) << 32) | step_tag.
// Double-buffered by step parity; a single relaxed 64-bit store publishes
// value+tag atomically -> no fences anywhere. Reset kernel restores tags each
// launch so graph replays are deterministic. (R5 protocol, proven.)
// R17: X is staged through SMEM in 8-step batches (loaded once per CTA
// instead of once per warp -> 8x less global x traffic, and no per-step DRAM
// loads sharing the LSU queue with poll retries).
__device__ unsigned long long g_hbuf[2][HID];

__device__ __forceinline__ unsigned long long ldx(const unsigned long long* p) {
    unsigned long long v;
    asm volatile("ld.relaxed.gpu.global.b64 %0, [%1];" : "=l"(v) : "l"(p));
    return v;
}
__device__ __forceinline__ void stx(unsigned long long* p, unsigned long long v) {
    asm volatile("st.relaxed.gpu.global.b64 [%0], %1;" :: "l"(p), "l"(v) : "memory");
}
__device__ __forceinline__ unsigned long long packh(float h, unsigned tag) {
    return ((unsigned long long)__float_as_uint(h) << 32) | (unsigned long long)tag;
}
__device__ __forceinline__ float unpackh(unsigned long long v) {
    return __uint_as_float((unsigned)(v >> 32));
}
__device__ __forceinline__ float tanh_fast(float v) {
    float r;
    asm volatile("tanh.approx.f32 %0, %1;" : "=f"(r) : "f"(v));
    return r;
}

__global__ void rnn_reset_kernel() {
    int t = threadIdx.x;
    unsigned long long z = packh(0.0f, 0u);   // h0 = 0, tag 0
    for (int i = t; i < 2 * HID; i += blockDim.x)
        ((unsigned long long*)g_hbuf)[i] = z;
}

__global__ void __launch_bounds__(TPB, 1) rnn_scan_kernel(
    const float* __restrict__ X,    // [T, 1, 256]
    const float* __restrict__ Wi,   // [1024, 256]
    const float* __restrict__ bi,   // [1024]
    const float* __restrict__ Wh,   // [1024, 1024]
    const float* __restrict__ bh,   // [1024]
    const float* __restrict__ Wo,   // [32, 1024]
    const float* __restrict__ bo,   // [32]
    float* __restrict__ out)        // [32] log-softmax
{
    const int t    = threadIdx.x;
    const int lane = t & 31;
    const int warp = t >> 5;
    const int row  = blockIdx.x * WPC + warp;   // this warp's hidden row

    // Double-buffered plain-float h staged per CTA. One barrier per step.
    __shared__ float sh[2][HID];
    // Double-buffered 8-step x batches (2KB each), swapped every 8 steps.
    __shared__ float sx[2][8][INP];

    // ---- Register-resident weights (held for all 16384 steps) ----
    // Lane l owns hidden columns (k/4)*128 + 4l + (k%4), k=0..31 (float4-
    // contiguous groups -> 8x LDS.128 per step) and the analogous 8 input cols.
    float w[32];
    #pragma unroll
    for (int k = 0; k < 32; k++)
        w[k] = Wh[row * HID + (k >> 2) * 128 + 4 * lane + (k & 3)];
    float wi[8];
    #pragma unroll
    for (int k = 0; k < 8; k++)
        wi[k] = Wi[row * INP + (k >> 2) * 128 + 4 * lane + (k & 3)];
    const float bias = bi[row] + bh[row];

    // ---- Prologue: stage x for steps 0..7 into buffer 0. ----
    #pragma unroll
    for (int k = 0; k < 8; k++)
        sx[0][k][t] = X[k * INP + t];
    __syncthreads();

    for (int s = 0; s < T_STEPS; s++) {
        const int buf = s & 1;
        const unsigned tag = (unsigned)s;
        const unsigned long long* hb = g_hbuf[buf];

        // ---- Poll phase: issue all 4 word loads first (R5-identical). ----
        unsigned long long v[WPT];
        #pragma unroll
        for (int i = 0; i < WPT; i++) v[i] = ldx(hb + t + TPB * i);

        // x for THIS step from SMEM (2x conflict-free LDS.128; no LDG).
        const float* xs = sx[(s >> 3) & 1][s & 7];
        float4 x0a = *(const float4*)(xs + 4 * lane);
        float4 x0b = *(const float4*)(xs + 128 + 4 * lane);

        // Input projection for THIS step while polls are in flight.
        float a0 = (lane == 0) ? bias : 0.0f;
        float a1 = 0.f, a2 = 0.f, a3 = 0.f;
        a0 = fmaf(wi[0], x0a.x, a0);  a1 = fmaf(wi[1], x0a.y, a1);
        a2 = fmaf(wi[2], x0a.z, a2);  a3 = fmaf(wi[3], x0a.w, a3);
        a0 = fmaf(wi[4], x0b.x, a0);  a1 = fmaf(wi[5], x0b.y, a1);
        a2 = fmaf(wi[6], x0b.z, a2);  a3 = fmaf(wi[7], x0b.w, a3);

        // Resolve tags: retry only stale words (tags monotone, <= s).
        for (;;) {
            unsigned bad = 0;
            #pragma unroll
            for (int i = 0; i < WPT; i++) bad |= ((unsigned)v[i]) ^ tag;
            if (bad == 0) break;
            #pragma unroll
            for (int i = 0; i < WPT; i++)
                if (((unsigned)v[i]) != tag) v[i] = ldx(hb + t + TPB * i);
        }
        #pragma unroll
        for (int i = 0; i < WPT; i++) sh[buf][t + TPB * i] = unpackh(v[i]);

        __syncthreads();   // the only barrier per step

        // ---- Once per 8 steps: stage the NEXT x batch (steps s+8..s+15)
        // into the other buffer. Issued after the barrier, overlapped with
        // the GEMV; 8 intervening barriers order these writes before any
        // read of that buffer. Coalesced, once per CTA (not per warp). ----
        if ((s & 7) == 0 && s + 8 < T_STEPS) {
            int nb = ((s >> 3) + 1) & 1;
            #pragma unroll
            for (int k = 0; k < 8; k++)
                sx[nb][k][t] = X[(s + 8 + k) * INP + t];
        }

        // ---- Recurrent GEMV: 8x LDS.128 + 32 FMA (R5-identical). ----
        const float* hs = sh[buf];
        #pragma unroll
        for (int g = 0; g < 8; g++) {
            float4 h4 = *(const float4*)(hs + g * 128 + 4 * lane);
            a0 = fmaf(w[4 * g + 0], h4.x, a0);
            a1 = fmaf(w[4 * g + 1], h4.y, a1);
            a2 = fmaf(w[4 * g + 2], h4.z, a2);
            a3 = fmaf(w[4 * g + 3], h4.w, a3);
        }
        float acc = (a0 + a1) + (a2 + a3);
        #pragma unroll
        for (int off = 16; off > 0; off >>= 1)
            acc += __shfl_xor_sync(0xffffffffu, acc, off);

        if (lane == 0) {
            float hnew = tanh_fast(acc);
            stx(&g_hbuf[buf ^ 1][row], packh(hnew, tag + 1u));
        }
    }

    // ---- Epilogue: CTA 0 computes logits + log_softmax on h_T ----
    if (blockIdx.x == 0) {
        for (int j = t; j < HID; j += TPB) {
            unsigned long long vv = ldx(&g_hbuf[0][j]);   // T even -> buffer 0
            while (((unsigned)vv) != (unsigned)T_STEPS) vv = ldx(&g_hbuf[0][j]);
            sh[0][j] = unpackh(vv);
        }
        __syncthreads();

        int orow = t >> 3;      // 32 rows x 8 threads
        int sub  = t & 7;
        float acc = 0.0f;
        #pragma unroll 4
        for (int j = 0; j < HID / 8; j += 4) {
            int col = sub * (HID / 8) + j;
            float4 w4 = ((const float4*)Wo)[(orow * HID + col) >> 2];
            acc = fmaf(w4.x, sh[0][col + 0], acc);
            acc = fmaf(w4.y, sh[0][col + 1], acc);
            acc = fmaf(w4.z, sh[0][col + 2], acc);
            acc = fmaf(w4.w, sh[0][col + 3], acc);
        }
        acc += __shfl_down_sync(0xffffffffu, acc, 4);
        acc += __shfl_down_sync(0xffffffffu, acc, 2);
        acc += __shfl_down_sync(0xffffffffu, acc, 1);

        __shared__ float s_log[NLAB];
        if (sub == 0) s_log[orow] = acc + bo[orow];
        __syncthreads();

        if (t < NLAB) {
            float vl = s_log[t];
            float m = vl;
            #pragma unroll
            for (int off = 16; off > 0; off >>= 1)
                m = fmaxf(m, __shfl_xor_sync(0xffffffffu, m, off));
            float e = expf(vl - m);
            float ssum = e;
            #pragma unroll
            for (int off = 16; off > 0; off >>= 1)
                ssum += __shfl_xor_sync(0xffffffffu, ssum, off);
            out[t] = vl - m - logf(ssum);
        }
    }
}

extern "C" void kernel_launch(void* const* d_in, const int* in_sizes, int n_in,
                              void* d_out, int out_size) {
    const float* X  = (const float*)d_in[0];
    const float* Wi = (const float*)d_in[1];
    const float* bi = (const float*)d_in[2];
    const float* Wh = (const float*)d_in[3];
    const float* bh = (const float*)d_in[4];
    const float* Wo = (const float*)d_in[5];
    const float* bo = (const float*)d_in[6];
    float* out = (float*)d_out;

    rnn_reset_kernel<<<1, 256>>>();
    rnn_scan_kernel<<<NCTA, TPB>>>(X, Wi, bi, Wh, bh, Wo, bo, out);
}